// round 1
// baseline (speedup 1.0000x reference)
#include <cuda_runtime.h>

// Problem constants
#define Bn   4
#define Nrois 32
#define Cc   256
#define HF   128
#define WF   128
#define Sx   64
#define CROPS_ELEMS ((size_t)128 * Cc * Sx * Sx)   // 134217728

__device__ __forceinline__ void roi_params(const float* __restrict__ obb, int r,
                                           float& cx, float& cy, float& wf, float& hf,
                                           float& c_, float& s_) {
    const float* o = obb + r * 5;
    cx = o[0] * 0.125f;
    cy = o[1] * 0.125f;
    wf = fmaxf(o[2], 1.0f) * (1.25f / 8.0f);
    hf = fmaxf(o[3], 1.0f) * (1.25f / 8.0f);
    float ang = o[4] * 0.017453292519943295f;  // deg2rad
    c_ = cosf(ang);
    s_ = sinf(ang);
}

// One thread per (roi, sy, sx); loops over all 256 channels.
// block = (64, 4): tx = sx, ty = sy sub-row. grid = (16, 128): bx = sy group, by = roi.
__global__ __launch_bounds__(256) void rotated_roi_pool_kernel(
    const float* __restrict__ feat,
    const float* __restrict__ obb,
    float* __restrict__ out)
{
    const int sx = threadIdx.x;                         // 0..63
    const int sy = blockIdx.x * blockDim.y + threadIdx.y; // 0..63
    const int r  = blockIdx.y;                          // 0..127
    const int b  = r >> 5;

    float cx, cy, wf, hf, c_, s_;
    roi_params(obb, r, cx, cy, wf, hf, c_, s_);

    // Affine grid coefficients
    const float sxs = wf * (2.0f / (float)WF);
    const float sys = hf * (2.0f / (float)HF);
    const float tx  = cx * (2.0f / (float)WF) - 1.0f;
    const float ty  = cy * (2.0f / (float)HF) - 1.0f;
    const float a11 = c_ * sxs, a12 = -s_ * sys, a13 = tx;
    const float a21 = s_ * sxs, a22 =  c_ * sys, a23 = ty;

    const float X = 2.0f * ((float)sx + 0.5f) / (float)Sx - 1.0f;
    const float Y = 2.0f * ((float)sy + 0.5f) / (float)Sx - 1.0f;

    const float gx = a11 * X + a12 * Y + a13;
    const float gy = a21 * X + a22 * Y + a23;

    const float ix = ((gx + 1.0f) * (float)WF - 1.0f) * 0.5f;
    const float iy = ((gy + 1.0f) * (float)HF - 1.0f) * 0.5f;

    const float x0f = floorf(ix);
    const float y0f = floorf(iy);
    const float wx = ix - x0f;
    const float wy = iy - y0f;

    const int x0 = (int)x0f;
    const int y0 = (int)y0f;
    const int x1 = x0 + 1;
    const int y1 = y0 + 1;

    // Validity folded into weights (== ref's v * valid * weight)
    const float vx0 = (x0 >= 0 && x0 < WF) ? 1.0f : 0.0f;
    const float vx1 = (x1 >= 0 && x1 < WF) ? 1.0f : 0.0f;
    const float vy0 = (y0 >= 0 && y0 < HF) ? 1.0f : 0.0f;
    const float vy1 = (y1 >= 0 && y1 < HF) ? 1.0f : 0.0f;

    const float w00 = (1.0f - wx) * (1.0f - wy) * vx0 * vy0;
    const float w01 = wx          * (1.0f - wy) * vx1 * vy0;
    const float w10 = (1.0f - wx) * wy          * vx0 * vy1;
    const float w11 = wx          * wy          * vx1 * vy1;

    const int xc0 = min(max(x0, 0), WF - 1);
    const int xc1 = min(max(x1, 0), WF - 1);
    const int yc0 = min(max(y0, 0), HF - 1);
    const int yc1 = min(max(y1, 0), HF - 1);

    const int off00 = yc0 * WF + xc0;
    const int off01 = yc0 * WF + xc1;
    const int off10 = yc1 * WF + xc0;
    const int off11 = yc1 * WF + xc1;

    const float* __restrict__ p = feat + (size_t)b * Cc * HF * WF;
    float* __restrict__ op = out + (size_t)r * Cc * Sx * Sx + (size_t)sy * Sx + sx;

    const int chStride = HF * WF;   // 16384 floats
    const int outStride = Sx * Sx;  // 4096 floats

    #pragma unroll 4
    for (int c = 0; c < Cc; ++c) {
        float f00 = __ldg(p + off00);
        float f01 = __ldg(p + off01);
        float f10 = __ldg(p + off10);
        float f11 = __ldg(p + off11);
        float v = w00 * f00;
        v = fmaf(w01, f01, v);
        v = fmaf(w10, f10, v);
        v = fmaf(w11, f11, v);
        *op = v;
        p  += chStride;
        op += outStride;
    }
}

// M_all: (128, 2, 3) appended after crops
__global__ void m_all_kernel(const float* __restrict__ obb, float* __restrict__ m)
{
    int r = threadIdx.x;
    if (r >= 128) return;

    float cx, cy, wf, hf, c_, s_;
    roi_params(obb, r, cx, cy, wf, hf, c_, s_);

    const float A  =  c_ * (wf / (float)Sx);
    const float Bv = -s_ * (hf / (float)Sx);
    const float A2 =  s_ * (wf / (float)Sx);
    const float B2 =  c_ * (hf / (float)Sx);
    const float Cx = cx - 0.5f * (float)Sx * (A + Bv);
    const float Cy = cy - 0.5f * (float)Sx * (A2 + B2);

    float* o = m + (size_t)r * 6;
    o[0] = A;  o[1] = Bv; o[2] = Cx;
    o[3] = A2; o[4] = B2; o[5] = Cy;
}

extern "C" void kernel_launch(void* const* d_in, const int* in_sizes, int n_in,
                              void* d_out, int out_size) {
    const float* feat = (const float*)d_in[0];
    const float* obb  = (const float*)d_in[1];
    float* out = (float*)d_out;

    dim3 block(64, 4, 1);
    dim3 grid(16, 128, 1);
    rotated_roi_pool_kernel<<<grid, block>>>(feat, obb, out);
    m_all_kernel<<<1, 128>>>(obb, out + CROPS_ELEMS);
}

// round 3
// speedup vs baseline: 1.8864x; 1.8864x over previous
#include <cuda_runtime.h>

// Problem constants
#define Bn    4
#define Cc    256
#define HF    128
#define WF    128
#define Sx    64
#define CROPS_ELEMS ((size_t)128 * Cc * Sx * Sx)   // 134217728

// Scratch: feat transposed to NHWC [b][y][x][c], c contiguous (67 MB)
__device__ float g_nhwc[(size_t)Bn * HF * WF * Cc];

__device__ __forceinline__ void roi_params(const float* __restrict__ obb, int r,
                                           float& cx, float& cy, float& wf, float& hf,
                                           float& c_, float& s_) {
    const float* o = obb + r * 5;
    cx = o[0] * 0.125f;
    cy = o[1] * 0.125f;
    wf = fmaxf(o[2], 1.0f) * (1.25f / 8.0f);
    hf = fmaxf(o[3], 1.0f) * (1.25f / 8.0f);
    float ang = o[4] * 0.017453292519943295f;  // deg2rad
    c_ = cosf(ang);
    s_ = sinf(ang);
}

// ---------------------------------------------------------------------------
// Kernel 1: NCHW -> NHWC transpose. Block (32,8), 32x32 (c,x) tiles.
// grid: x = x-tile (4), y = c-tile (8), z = b*HF + y (512)
// ---------------------------------------------------------------------------
__global__ __launch_bounds__(256) void transpose_kernel(const float* __restrict__ feat)
{
    __shared__ float ts[32][33];
    const int tx = threadIdx.x, ty = threadIdx.y;
    const int bz = blockIdx.z;
    const int b = bz >> 7;          // /128
    const int y = bz & 127;

    const int x_in = blockIdx.x * 32 + tx;
    #pragma unroll
    for (int j = 0; j < 4; ++j) {
        int c = blockIdx.y * 32 + ty + j * 8;
        ts[ty + j * 8][tx] = __ldcs(&feat[(((size_t)(b * Cc + c) * HF + y) * WF) + x_in]);
    }
    __syncthreads();

    const int c_out = blockIdx.y * 32 + tx;
    #pragma unroll
    for (int j = 0; j < 4; ++j) {
        int x = blockIdx.x * 32 + ty + j * 8;
        g_nhwc[(((size_t)(b * HF + y) * WF + x) * Cc) + c_out] = ts[tx][ty + j * 8];
    }
}

// ---------------------------------------------------------------------------
// Kernel 2: pooling. One block per (roi, sy): 256 threads.
//   Phase 0: threads 0..63 compute per-sx taps/weights.
//   Per 128-channel slab (2 slabs):
//     compute: warp w handles points i = w*8+j; lanes = float4 channel chunks.
//              4 dense LDG.128 per (point, tap); STS.128 to tile.
//     store:   lanes = sx; LDS.128 (conflict-free via 132-float row stride);
//              4 coalesced STG.32 per float4, streaming (__stcs).
// ---------------------------------------------------------------------------
__global__ __launch_bounds__(256) void rotated_roi_pool_kernel(
    const float* __restrict__ obb,
    float* __restrict__ out)
{
    __shared__ int   o00[Sx], o01[Sx], o10[Sx], o11[Sx];   // float4-unit pixel bases
    __shared__ float w00s[Sx], w01s[Sx], w10s[Sx], w11s[Sx];
    __shared__ float tile[Sx * 132];                       // [sx][132] floats

    const int t    = threadIdx.x;
    const int sy   = blockIdx.x;
    const int r    = blockIdx.y;
    const int b    = r >> 5;
    const int warp = t >> 5;
    const int lane = t & 31;

    // ---- Phase 0: per-sample-point coordinates ----
    if (t < Sx) {
        const int sx = t;
        float cx, cy, wf, hf, c_, s_;
        roi_params(obb, r, cx, cy, wf, hf, c_, s_);

        const float sxs = wf * (2.0f / (float)WF);
        const float sys = hf * (2.0f / (float)HF);
        const float txc = cx * (2.0f / (float)WF) - 1.0f;
        const float tyc = cy * (2.0f / (float)HF) - 1.0f;
        const float a11 = c_ * sxs, a12 = -s_ * sys;
        const float a21 = s_ * sxs, a22 =  c_ * sys;

        const float X = 2.0f * ((float)sx + 0.5f) / (float)Sx - 1.0f;
        const float Y = 2.0f * ((float)sy + 0.5f) / (float)Sx - 1.0f;

        const float gx = a11 * X + a12 * Y + txc;
        const float gy = a21 * X + a22 * Y + tyc;

        const float ix = ((gx + 1.0f) * (float)WF - 1.0f) * 0.5f;
        const float iy = ((gy + 1.0f) * (float)HF - 1.0f) * 0.5f;

        const float x0f = floorf(ix);
        const float y0f = floorf(iy);
        const float wx = ix - x0f;
        const float wy = iy - y0f;

        const int x0 = (int)x0f, y0 = (int)y0f;
        const int x1 = x0 + 1,   y1 = y0 + 1;

        const float vx0 = (x0 >= 0 && x0 < WF) ? 1.0f : 0.0f;
        const float vx1 = (x1 >= 0 && x1 < WF) ? 1.0f : 0.0f;
        const float vy0 = (y0 >= 0 && y0 < HF) ? 1.0f : 0.0f;
        const float vy1 = (y1 >= 0 && y1 < HF) ? 1.0f : 0.0f;

        w00s[sx] = (1.0f - wx) * (1.0f - wy) * vx0 * vy0;
        w01s[sx] = wx          * (1.0f - wy) * vx1 * vy0;
        w10s[sx] = (1.0f - wx) * wy          * vx0 * vy1;
        w11s[sx] = wx          * wy          * vx1 * vy1;

        const int xc0 = min(max(x0, 0), WF - 1);
        const int xc1 = min(max(x1, 0), WF - 1);
        const int yc0 = min(max(y0, 0), HF - 1);
        const int yc1 = min(max(y1, 0), HF - 1);

        const int base = b * HF * WF;  // pixels
        // float4-unit offsets: pixel * (Cc/4)
        o00[sx] = (base + yc0 * WF + xc0) * (Cc / 4);
        o01[sx] = (base + yc0 * WF + xc1) * (Cc / 4);
        o10[sx] = (base + yc1 * WF + xc0) * (Cc / 4);
        o11[sx] = (base + yc1 * WF + xc1) * (Cc / 4);
    }
    __syncthreads();

    const float4* __restrict__ nhwc4 = reinterpret_cast<const float4*>(g_nhwc);
    const int sx_st = t & 63;   // store-phase sx
    const int cg    = t >> 6;   // store-phase channel group (0..3)

    #pragma unroll
    for (int slab = 0; slab < 2; ++slab) {
        const int chunk_base = slab * 32;  // float4 chunk offset within pixel

        // ---- compute phase: warp w -> points w*8 .. w*8+7 ----
        #pragma unroll
        for (int j = 0; j < 8; ++j) {
            const int i = warp * 8 + j;
            const int co = chunk_base + lane;
            float4 f00 = __ldg(&nhwc4[o00[i] + co]);
            float4 f01 = __ldg(&nhwc4[o01[i] + co]);
            float4 f10 = __ldg(&nhwc4[o10[i] + co]);
            float4 f11 = __ldg(&nhwc4[o11[i] + co]);
            const float a = w00s[i], b_ = w01s[i], c2 = w10s[i], d = w11s[i];
            float4 v;
            v.x = fmaf(d, f11.x, fmaf(c2, f10.x, fmaf(b_, f01.x, a * f00.x)));
            v.y = fmaf(d, f11.y, fmaf(c2, f10.y, fmaf(b_, f01.y, a * f00.y)));
            v.z = fmaf(d, f11.z, fmaf(c2, f10.z, fmaf(b_, f01.z, a * f00.z)));
            v.w = fmaf(d, f11.w, fmaf(c2, f10.w, fmaf(b_, f01.w, a * f00.w)));
            // tile[i][4*lane .. 4*lane+3]
            *reinterpret_cast<float4*>(&tile[i * 132 + 4 * lane]) = v;
        }
        __syncthreads();

        // ---- store phase: lanes = sx, coalesced streaming stores ----
        #pragma unroll
        for (int j = 0; j < 8; ++j) {
            const int chunk = cg * 8 + j;          // 0..31
            float4 v = *reinterpret_cast<const float4*>(&tile[sx_st * 132 + 4 * chunk]);
            const int c_global = slab * 128 + 4 * chunk;
            float* op = out + (((size_t)(r * Cc + c_global) * Sx + sy) * Sx) + sx_st;
            __stcs(op,                 v.x);
            __stcs(op + 1 * Sx * Sx,   v.y);
            __stcs(op + 2 * Sx * Sx,   v.z);
            __stcs(op + 3 * Sx * Sx,   v.w);
        }
        __syncthreads();
    }
}

// ---------------------------------------------------------------------------
// M_all: (128, 2, 3) appended after crops
// ---------------------------------------------------------------------------
__global__ void m_all_kernel(const float* __restrict__ obb, float* __restrict__ m)
{
    int r = threadIdx.x;
    if (r >= 128) return;

    float cx, cy, wf, hf, c_, s_;
    roi_params(obb, r, cx, cy, wf, hf, c_, s_);

    const float A  =  c_ * (wf / (float)Sx);
    const float Bv = -s_ * (hf / (float)Sx);
    const float A2 =  s_ * (wf / (float)Sx);
    const float B2 =  c_ * (hf / (float)Sx);
    const float Cx = cx - 0.5f * (float)Sx * (A + Bv);
    const float Cy = cy - 0.5f * (float)Sx * (A2 + B2);

    float* o = m + (size_t)r * 6;
    o[0] = A;  o[1] = Bv; o[2] = Cx;
    o[3] = A2; o[4] = B2; o[5] = Cy;
}

extern "C" void kernel_launch(void* const* d_in, const int* in_sizes, int n_in,
                              void* d_out, int out_size) {
    const float* feat = (const float*)d_in[0];
    const float* obb  = (const float*)d_in[1];
    float* out = (float*)d_out;

    dim3 tb(32, 8, 1);
    dim3 tg(WF / 32, Cc / 32, Bn * HF);   // (4, 8, 512)
    transpose_kernel<<<tg, tb>>>(feat);

    dim3 grid(Sx, 128, 1);                // (sy, roi)
    rotated_roi_pool_kernel<<<grid, 256>>>(obb, out);

    m_all_kernel<<<1, 128>>>(obb, out + CROPS_ELEMS);
}

// round 5
// speedup vs baseline: 2.1520x; 1.1408x over previous
#include <cuda_runtime.h>

// Problem constants
#define Bn    4
#define Cc    256
#define HF    128
#define WF    128
#define Sx    64
#define CROPS_ELEMS ((size_t)128 * Cc * Sx * Sx)   // 134217728

// Scratch: feat transposed to NHWC [b][y][x][c], c contiguous (67 MB)
__device__ float g_nhwc[(size_t)Bn * HF * WF * Cc];

__device__ __forceinline__ void roi_params(const float* __restrict__ obb, int r,
                                           float& cx, float& cy, float& wf, float& hf,
                                           float& c_, float& s_) {
    const float* o = obb + r * 5;
    cx = o[0] * 0.125f;
    cy = o[1] * 0.125f;
    wf = fmaxf(o[2], 1.0f) * (1.25f / 8.0f);
    hf = fmaxf(o[3], 1.0f) * (1.25f / 8.0f);
    float ang = o[4] * 0.017453292519943295f;  // deg2rad
    c_ = cosf(ang);
    s_ = sinf(ang);
}

// ---------------------------------------------------------------------------
// Kernel 1: NCHW -> NHWC transpose. Block (32,8), 32x32 (c,x) tiles.
// Already wavefront-minimal (coalesced 128B loads + stores); leave as-is.
// ---------------------------------------------------------------------------
__global__ __launch_bounds__(256) void transpose_kernel(const float* __restrict__ feat)
{
    __shared__ float ts[32][33];
    const int tx = threadIdx.x, ty = threadIdx.y;
    const int bz = blockIdx.z;
    const int b = bz >> 7;          // /128
    const int y = bz & 127;

    const int x_in = blockIdx.x * 32 + tx;
    #pragma unroll
    for (int j = 0; j < 4; ++j) {
        int c = blockIdx.y * 32 + ty + j * 8;
        ts[ty + j * 8][tx] = __ldcs(&feat[(((size_t)(b * Cc + c) * HF + y) * WF) + x_in]);
    }
    __syncthreads();

    const int c_out = blockIdx.y * 32 + tx;
    #pragma unroll
    for (int j = 0; j < 4; ++j) {
        int x = blockIdx.x * 32 + ty + j * 8;
        g_nhwc[(((size_t)(b * HF + y) * WF + x) * Cc) + c_out] = ts[tx][ty + j * 8];
    }
}

// ---------------------------------------------------------------------------
// Kernel 2: pooling. One block per (roi, sy): 256 threads.
//   Compute phase: warp w handles 8 consecutive points; lanes = float4 ch
//   chunks. Tap-reuse: consecutive points usually sample the SAME 4 feat
//   pixels (step = wf/64 <= 0.49 px), so we skip the 4x LDG.128 when the
//   tap-offset set is unchanged, and register-shift on single x/y advances.
//   All reuse conditions are warp-uniform -> no divergence.
// ---------------------------------------------------------------------------
__global__ __launch_bounds__(256) void rotated_roi_pool_kernel(
    const float* __restrict__ obb,
    float* __restrict__ out)
{
    __shared__ int   o00[Sx], o01[Sx], o10[Sx], o11[Sx];   // float4-unit pixel bases
    __shared__ float w00s[Sx], w01s[Sx], w10s[Sx], w11s[Sx];
    __shared__ float tile[Sx * 132];                       // [sx][132] floats

    const int t    = threadIdx.x;
    const int sy   = blockIdx.x;
    const int r    = blockIdx.y;
    const int b    = r >> 5;
    const int warp = t >> 5;
    const int lane = t & 31;

    // ---- Phase 0: per-sample-point coordinates ----
    if (t < Sx) {
        const int sx = t;
        float cx, cy, wf, hf, c_, s_;
        roi_params(obb, r, cx, cy, wf, hf, c_, s_);

        const float sxs = wf * (2.0f / (float)WF);
        const float sys = hf * (2.0f / (float)HF);
        const float txc = cx * (2.0f / (float)WF) - 1.0f;
        const float tyc = cy * (2.0f / (float)HF) - 1.0f;
        const float a11 = c_ * sxs, a12 = -s_ * sys;
        const float a21 = s_ * sxs, a22 =  c_ * sys;

        const float X = 2.0f * ((float)sx + 0.5f) / (float)Sx - 1.0f;
        const float Y = 2.0f * ((float)sy + 0.5f) / (float)Sx - 1.0f;

        const float gx = a11 * X + a12 * Y + txc;
        const float gy = a21 * X + a22 * Y + tyc;

        const float ix = ((gx + 1.0f) * (float)WF - 1.0f) * 0.5f;
        const float iy = ((gy + 1.0f) * (float)HF - 1.0f) * 0.5f;

        const float x0f = floorf(ix);
        const float y0f = floorf(iy);
        const float wx = ix - x0f;
        const float wy = iy - y0f;

        const int x0 = (int)x0f, y0 = (int)y0f;
        const int x1 = x0 + 1,   y1 = y0 + 1;

        const float vx0 = (x0 >= 0 && x0 < WF) ? 1.0f : 0.0f;
        const float vx1 = (x1 >= 0 && x1 < WF) ? 1.0f : 0.0f;
        const float vy0 = (y0 >= 0 && y0 < HF) ? 1.0f : 0.0f;
        const float vy1 = (y1 >= 0 && y1 < HF) ? 1.0f : 0.0f;

        w00s[sx] = (1.0f - wx) * (1.0f - wy) * vx0 * vy0;
        w01s[sx] = wx          * (1.0f - wy) * vx1 * vy0;
        w10s[sx] = (1.0f - wx) * wy          * vx0 * vy1;
        w11s[sx] = wx          * wy          * vx1 * vy1;

        const int xc0 = min(max(x0, 0), WF - 1);
        const int xc1 = min(max(x1, 0), WF - 1);
        const int yc0 = min(max(y0, 0), HF - 1);
        const int yc1 = min(max(y1, 0), HF - 1);

        const int base = b * HF * WF;  // pixels
        o00[sx] = (base + yc0 * WF + xc0) * (Cc / 4);
        o01[sx] = (base + yc0 * WF + xc1) * (Cc / 4);
        o10[sx] = (base + yc1 * WF + xc0) * (Cc / 4);
        o11[sx] = (base + yc1 * WF + xc1) * (Cc / 4);
    }
    __syncthreads();

    const float4* __restrict__ nhwc4 = reinterpret_cast<const float4*>(g_nhwc);
    const int sx_st = t & 63;   // store-phase sx
    const int cg    = t >> 6;   // store-phase channel group (0..3)

    #pragma unroll
    for (int slab = 0; slab < 2; ++slab) {
        const int co = slab * 32 + lane;  // float4 chunk within pixel

        // ---- compute phase with tap-reuse ----
        int p00 = -1, p01 = -1, p10 = -1, p11 = -1;
        float4 f00 = {0,0,0,0}, f01 = {0,0,0,0}, f10 = {0,0,0,0}, f11 = {0,0,0,0};

        #pragma unroll
        for (int j = 0; j < 8; ++j) {
            const int i = warp * 8 + j;
            const int q00 = o00[i], q01 = o01[i], q10 = o10[i], q11 = o11[i];

            // warp-uniform reuse logic
            if (q00 == p00 && q01 == p01 && q10 == p10 && q11 == p11) {
                // identical tap set: reuse all 4 registers, no loads
            } else if (q00 == p01 && q10 == p11) {
                // x-advance: left taps = previous right taps
                f00 = f01; f10 = f11;
                f01 = __ldg(&nhwc4[q01 + co]);
                f11 = __ldg(&nhwc4[q11 + co]);
            } else if (q00 == p10 && q01 == p11) {
                // y-advance: top taps = previous bottom taps
                f00 = f10; f01 = f11;
                f10 = __ldg(&nhwc4[q10 + co]);
                f11 = __ldg(&nhwc4[q11 + co]);
            } else {
                f00 = __ldg(&nhwc4[q00 + co]);
                f01 = __ldg(&nhwc4[q01 + co]);
                f10 = __ldg(&nhwc4[q10 + co]);
                f11 = __ldg(&nhwc4[q11 + co]);
            }
            p00 = q00; p01 = q01; p10 = q10; p11 = q11;

            const float a = w00s[i], b_ = w01s[i], c2 = w10s[i], d = w11s[i];
            float4 v;
            v.x = fmaf(d, f11.x, fmaf(c2, f10.x, fmaf(b_, f01.x, a * f00.x)));
            v.y = fmaf(d, f11.y, fmaf(c2, f10.y, fmaf(b_, f01.y, a * f00.y)));
            v.z = fmaf(d, f11.z, fmaf(c2, f10.z, fmaf(b_, f01.z, a * f00.z)));
            v.w = fmaf(d, f11.w, fmaf(c2, f10.w, fmaf(b_, f01.w, a * f00.w)));
            *reinterpret_cast<float4*>(&tile[i * 132 + 4 * lane]) = v;
        }
        __syncthreads();

        // ---- store phase: lanes = sx, coalesced streaming stores ----
        #pragma unroll
        for (int j = 0; j < 8; ++j) {
            const int chunk = cg * 8 + j;          // 0..31
            float4 v = *reinterpret_cast<const float4*>(&tile[sx_st * 132 + 4 * chunk]);
            const int c_global = slab * 128 + 4 * chunk;
            float* op = out + (((size_t)(r * Cc + c_global) * Sx + sy) * Sx) + sx_st;
            __stcs(op,                 v.x);
            __stcs(op + 1 * Sx * Sx,   v.y);
            __stcs(op + 2 * Sx * Sx,   v.z);
            __stcs(op + 3 * Sx * Sx,   v.w);
        }
        __syncthreads();
    }
}

// ---------------------------------------------------------------------------
// M_all: (128, 2, 3) appended after crops
// ---------------------------------------------------------------------------
__global__ void m_all_kernel(const float* __restrict__ obb, float* __restrict__ m)
{
    int r = threadIdx.x;
    if (r >= 128) return;

    float cx, cy, wf, hf, c_, s_;
    roi_params(obb, r, cx, cy, wf, hf, c_, s_);

    const float A  =  c_ * (wf / (float)Sx);
    const float Bv = -s_ * (hf / (float)Sx);
    const float A2 =  s_ * (wf / (float)Sx);
    const float B2 =  c_ * (hf / (float)Sx);
    const float Cx = cx - 0.5f * (float)Sx * (A + Bv);
    const float Cy = cy - 0.5f * (float)Sx * (A2 + B2);

    float* o = m + (size_t)r * 6;
    o[0] = A;  o[1] = Bv; o[2] = Cx;
    o[3] = A2; o[4] = B2; o[5] = Cy;
}

extern "C" void kernel_launch(void* const* d_in, const int* in_sizes, int n_in,
                              void* d_out, int out_size) {
    const float* feat = (const float*)d_in[0];
    const float* obb  = (const float*)d_in[1];
    float* out = (float*)d_out;

    dim3 tb(32, 8, 1);
    dim3 tg(WF / 32, Cc / 32, Bn * HF);   // (4, 8, 512)
    transpose_kernel<<<tg, tb>>>(feat);

    dim3 grid(Sx, 128, 1);                // (sy, roi)
    rotated_roi_pool_kernel<<<grid, 256>>>(obb, out);

    m_all_kernel<<<1, 128>>>(obb, out + CROPS_ELEMS);
}

// round 6
// speedup vs baseline: 2.1945x; 1.0197x over previous
#include <cuda_runtime.h>

// Problem constants
#define Bn    4
#define Cc    256
#define HF    128
#define WF    128
#define Sx    64
#define CROPS_ELEMS ((size_t)128 * Cc * Sx * Sx)   // 134217728

// Scratch: feat transposed to NHWC [b][y][x][c], c contiguous (67 MB)
__device__ float g_nhwc[(size_t)Bn * HF * WF * Cc];

__device__ __forceinline__ void roi_params(const float* __restrict__ obb, int r,
                                           float& cx, float& cy, float& wf, float& hf,
                                           float& c_, float& s_) {
    const float* o = obb + r * 5;
    cx = o[0] * 0.125f;
    cy = o[1] * 0.125f;
    wf = fmaxf(o[2], 1.0f) * (1.25f / 8.0f);
    hf = fmaxf(o[3], 1.0f) * (1.25f / 8.0f);
    float ang = o[4] * 0.017453292519943295f;  // deg2rad
    c_ = cosf(ang);
    s_ = sinf(ang);
}

// ---------------------------------------------------------------------------
// Kernel 1: NCHW -> NHWC transpose, vectorized.
// Block (8,32): tx = x-float4 (8 -> 32 x), ty = channel (32).
// grid: x = x-tile (4), y = c-tile (8), z = b*HF + y (512)
// Per thread: 1 LDG.128 + 4 STS.32 (conflict-free) + 4 LDS.32 (conflict-free)
//             + 1 STG.128 (contiguous 128B per 8-lane group).
// ---------------------------------------------------------------------------
__global__ __launch_bounds__(256) void transpose_kernel(const float* __restrict__ feat)
{
    __shared__ float ts[32 * 33];     // [x_local][c_local], stride 33
    const int tx = threadIdx.x;       // 0..7
    const int ty = threadIdx.y;       // 0..31
    const int bz = blockIdx.z;
    const int b = bz >> 7;
    const int y = bz & 127;

    const int c = blockIdx.y * 32 + ty;
    const float4* feat4 = reinterpret_cast<const float4*>(feat);
    float4 v = __ldcs(&feat4[((size_t)(b * Cc + c) * HF + y) * (WF / 4) + blockIdx.x * 8 + tx]);

    // transposed store: ts[x_local = 4tx+i][ty]; banks (4tx+i+ty) distinct per warp
    ts[(4 * tx + 0) * 33 + ty] = v.x;
    ts[(4 * tx + 1) * 33 + ty] = v.y;
    ts[(4 * tx + 2) * 33 + ty] = v.z;
    ts[(4 * tx + 3) * 33 + ty] = v.w;
    __syncthreads();

    // read back: pixel x_local = ty, channel chunk = tx (4 channels)
    float4 o;
    o.x = ts[ty * 33 + 4 * tx + 0];
    o.y = ts[ty * 33 + 4 * tx + 1];
    o.z = ts[ty * 33 + 4 * tx + 2];
    o.w = ts[ty * 33 + 4 * tx + 3];

    float4* nh4 = reinterpret_cast<float4*>(g_nhwc);
    const int x = blockIdx.x * 32 + ty;
    nh4[((size_t)(b * HF + y) * WF + x) * (Cc / 4) + blockIdx.y * 8 + tx] = o;
}

// ---------------------------------------------------------------------------
// Kernel 2: pooling. One block per (roi, sy): 256 threads.
//   Compute phase: warp w handles 8 consecutive points; lanes = float4 ch
//   chunks. Tap-reuse with DISTANCE-1 SOFTWARE PIPELINE: iteration j issues
//   the (branchy, warp-uniform) loads for point j+1 into 'n' registers,
//   computes point j from 'c' registers, then shifts. Loads are never
//   consumed in the iteration that issues them -> latency hidden.
// ---------------------------------------------------------------------------
__global__ __launch_bounds__(256) void rotated_roi_pool_kernel(
    const float* __restrict__ obb,
    float* __restrict__ out)
{
    __shared__ int   o00[Sx], o01[Sx], o10[Sx], o11[Sx];   // float4-unit pixel bases
    __shared__ float w00s[Sx], w01s[Sx], w10s[Sx], w11s[Sx];
    __shared__ float tile[Sx * 132];                       // [point][132] floats

    const int t    = threadIdx.x;
    const int sy   = blockIdx.x;
    const int r    = blockIdx.y;
    const int b    = r >> 5;
    const int warp = t >> 5;
    const int lane = t & 31;

    // ---- Phase 0: per-sample-point coordinates ----
    if (t < Sx) {
        const int sx = t;
        float cx, cy, wf, hf, c_, s_;
        roi_params(obb, r, cx, cy, wf, hf, c_, s_);

        const float sxs = wf * (2.0f / (float)WF);
        const float sys = hf * (2.0f / (float)HF);
        const float txc = cx * (2.0f / (float)WF) - 1.0f;
        const float tyc = cy * (2.0f / (float)HF) - 1.0f;
        const float a11 = c_ * sxs, a12 = -s_ * sys;
        const float a21 = s_ * sxs, a22 =  c_ * sys;

        const float X = 2.0f * ((float)sx + 0.5f) / (float)Sx - 1.0f;
        const float Y = 2.0f * ((float)sy + 0.5f) / (float)Sx - 1.0f;

        const float gx = a11 * X + a12 * Y + txc;
        const float gy = a21 * X + a22 * Y + tyc;

        const float ix = ((gx + 1.0f) * (float)WF - 1.0f) * 0.5f;
        const float iy = ((gy + 1.0f) * (float)HF - 1.0f) * 0.5f;

        const float x0f = floorf(ix);
        const float y0f = floorf(iy);
        const float wx = ix - x0f;
        const float wy = iy - y0f;

        const int x0 = (int)x0f, y0 = (int)y0f;
        const int x1 = x0 + 1,   y1 = y0 + 1;

        const float vx0 = (x0 >= 0 && x0 < WF) ? 1.0f : 0.0f;
        const float vx1 = (x1 >= 0 && x1 < WF) ? 1.0f : 0.0f;
        const float vy0 = (y0 >= 0 && y0 < HF) ? 1.0f : 0.0f;
        const float vy1 = (y1 >= 0 && y1 < HF) ? 1.0f : 0.0f;

        w00s[sx] = (1.0f - wx) * (1.0f - wy) * vx0 * vy0;
        w01s[sx] = wx          * (1.0f - wy) * vx1 * vy0;
        w10s[sx] = (1.0f - wx) * wy          * vx0 * vy1;
        w11s[sx] = wx          * wy          * vx1 * vy1;

        const int xc0 = min(max(x0, 0), WF - 1);
        const int xc1 = min(max(x1, 0), WF - 1);
        const int yc0 = min(max(y0, 0), HF - 1);
        const int yc1 = min(max(y1, 0), HF - 1);

        const int base = b * HF * WF;  // pixels
        o00[sx] = (base + yc0 * WF + xc0) * (Cc / 4);
        o01[sx] = (base + yc0 * WF + xc1) * (Cc / 4);
        o10[sx] = (base + yc1 * WF + xc0) * (Cc / 4);
        o11[sx] = (base + yc1 * WF + xc1) * (Cc / 4);
    }
    __syncthreads();

    const float4* __restrict__ nhwc4 = reinterpret_cast<const float4*>(g_nhwc);
    const int sx_st = t & 63;   // store-phase sx
    const int cg    = t >> 6;   // store-phase channel group (0..3)

    #pragma unroll
    for (int slab = 0; slab < 2; ++slab) {
        const int co    = slab * 32 + lane;  // float4 chunk within pixel
        const int ibase = warp * 8;

        // ---- compute phase: pipelined tap-reuse ----
        int p00 = o00[ibase], p01 = o01[ibase], p10 = o10[ibase], p11 = o11[ibase];
        float4 c00 = __ldg(&nhwc4[p00 + co]);
        float4 c01 = __ldg(&nhwc4[p01 + co]);
        float4 c10 = __ldg(&nhwc4[p10 + co]);
        float4 c11 = __ldg(&nhwc4[p11 + co]);

        #pragma unroll
        for (int j = 0; j < 8; ++j) {
            const int i = ibase + j;

            // Issue loads for point i+1 (fire-and-forget; consumed next iter)
            float4 n00, n01, n10, n11;
            int mode = 0;
            if (j < 7) {
                const int u00 = o00[i + 1], u01 = o01[i + 1];
                const int u10 = o10[i + 1], u11 = o11[i + 1];
                if (u00 == p00 && u01 == p01 && u10 == p10 && u11 == p11) {
                    mode = 0;   // identical tap set
                } else if (u00 == p01 && u10 == p11) {
                    n01 = __ldg(&nhwc4[u01 + co]);
                    n11 = __ldg(&nhwc4[u11 + co]);
                    mode = 1;   // x-advance
                } else if (u00 == p10 && u01 == p11) {
                    n10 = __ldg(&nhwc4[u10 + co]);
                    n11 = __ldg(&nhwc4[u11 + co]);
                    mode = 2;   // y-advance
                } else {
                    n00 = __ldg(&nhwc4[u00 + co]);
                    n01 = __ldg(&nhwc4[u01 + co]);
                    n10 = __ldg(&nhwc4[u10 + co]);
                    n11 = __ldg(&nhwc4[u11 + co]);
                    mode = 3;   // full reload
                }
                p00 = u00; p01 = u01; p10 = u10; p11 = u11;
            }

            // Compute point i from registers loaded >= 1 iteration ago
            const float a = w00s[i], b_ = w01s[i], c2 = w10s[i], d = w11s[i];
            float4 v;
            v.x = fmaf(d, c11.x, fmaf(c2, c10.x, fmaf(b_, c01.x, a * c00.x)));
            v.y = fmaf(d, c11.y, fmaf(c2, c10.y, fmaf(b_, c01.y, a * c00.y)));
            v.z = fmaf(d, c11.z, fmaf(c2, c10.z, fmaf(b_, c01.z, a * c00.z)));
            v.w = fmaf(d, c11.w, fmaf(c2, c10.w, fmaf(b_, c01.w, a * c00.w)));
            *reinterpret_cast<float4*>(&tile[i * 132 + 4 * lane]) = v;

            // Shift registers to match point i+1's tap set
            if (j < 7) {
                if (mode == 1)      { c00 = c01; c10 = c11; c01 = n01; c11 = n11; }
                else if (mode == 2) { c00 = c10; c01 = c11; c10 = n10; c11 = n11; }
                else if (mode == 3) { c00 = n00; c01 = n01; c10 = n10; c11 = n11; }
            }
        }
        __syncthreads();

        // ---- store phase: lanes = sx, coalesced streaming stores ----
        #pragma unroll
        for (int j = 0; j < 8; ++j) {
            const int chunk = cg * 8 + j;          // 0..31
            float4 v = *reinterpret_cast<const float4*>(&tile[sx_st * 132 + 4 * chunk]);
            const int c_global = slab * 128 + 4 * chunk;
            float* op = out + (((size_t)(r * Cc + c_global) * Sx + sy) * Sx) + sx_st;
            __stcs(op,               v.x);
            __stcs(op + 1 * Sx * Sx, v.y);
            __stcs(op + 2 * Sx * Sx, v.z);
            __stcs(op + 3 * Sx * Sx, v.w);
        }
        __syncthreads();
    }
}

// ---------------------------------------------------------------------------
// M_all: (128, 2, 3) appended after crops
// ---------------------------------------------------------------------------
__global__ void m_all_kernel(const float* __restrict__ obb, float* __restrict__ m)
{
    int r = threadIdx.x;
    if (r >= 128) return;

    float cx, cy, wf, hf, c_, s_;
    roi_params(obb, r, cx, cy, wf, hf, c_, s_);

    const float A  =  c_ * (wf / (float)Sx);
    const float Bv = -s_ * (hf / (float)Sx);
    const float A2 =  s_ * (wf / (float)Sx);
    const float B2 =  c_ * (hf / (float)Sx);
    const float Cx = cx - 0.5f * (float)Sx * (A + Bv);
    const float Cy = cy - 0.5f * (float)Sx * (A2 + B2);

    float* o = m + (size_t)r * 6;
    o[0] = A;  o[1] = Bv; o[2] = Cx;
    o[3] = A2; o[4] = B2; o[5] = Cy;
}

extern "C" void kernel_launch(void* const* d_in, const int* in_sizes, int n_in,
                              void* d_out, int out_size) {
    const float* feat = (const float*)d_in[0];
    const float* obb  = (const float*)d_in[1];
    float* out = (float*)d_out;

    dim3 tb(8, 32, 1);
    dim3 tg(WF / 32, Cc / 32, Bn * HF);   // (4, 8, 512)
    transpose_kernel<<<tg, tb>>>(feat);

    dim3 grid(Sx, 128, 1);                // (sy, roi)
    rotated_roi_pool_kernel<<<grid, 256>>>(obb, out);

    m_all_kernel<<<1, 128>>>(obb, out + CROPS_ELEMS);
}